// round 6
// baseline (speedup 1.0000x reference)
#include <cuda_runtime.h>
#include <cuda_bf16.h>
#include <cstdint>

#define S_LEN 2048
#define D_DIM 4096
#define H_Q   32
#define H_KV  8
#define HDIM  128
#define BATCH 2

#define KVTOT (BATCH * H_KV * S_LEN * HDIM)

// Scratch (allocation-free rule: __device__ globals)
__device__ float g_Q[BATCH * H_Q * S_LEN * HDIM];   // [B, H, S, HD]
__device__ float g_A[BATCH * S_LEN * H_Q * HDIM];   // [B, S, H, HD]
__device__ __nv_bfloat16 g_Kh[KVTOT], g_Kl[KVTOT];  // split K (post-RoPE)
__device__ __nv_bfloat16 g_Vh[KVTOT], g_Vl[KVTOT];  // split V

__device__ __forceinline__ uint32_t f2tf32(float f) {
    uint32_t u;
    asm("cvt.rna.tf32.f32 %0, %1;" : "=r"(u) : "f"(f));
    return u;
}
__device__ __forceinline__ void bsplit(float x, __nv_bfloat16& h, __nv_bfloat16& l) {
    h = __float2bfloat16(x);
    l = __float2bfloat16(x - __bfloat162float(h));
}
__device__ __forceinline__ uint32_t packbf(float a, float b) {
    __nv_bfloat162 t = __floats2bfloat162_rn(a, b);
    return *(uint32_t*)&t;
}

// ---------------------------------------------------------------------------
// TF32 NT GEMM, double-buffered smem pipeline. CTA 128x128, BK=32, 256 thr.
// mode 0: row-major store.  mode 1: head-permuted store to [B, HC, S, HD].
// ---------------------------------------------------------------------------
#define GSTRIDE 136
#define GSTAGE  (32 * GSTRIDE)               // words per operand per stage
#define GEMM_SMEM (2 * 2 * GSTAGE * 4)       // 69632 B

__global__ __launch_bounds__(256)
void tf32gemm_db(const float* __restrict__ A, const float* __restrict__ B,
                 float* __restrict__ C, int M, int N, int K, int mode, int HC)
{
    extern __shared__ uint32_t gsm[];
    // stage layout: [stage][A GSTAGE | B GSTAGE]
    const int tid = threadIdx.x;
    const int bm = blockIdx.y << 7;
    const int bn = blockIdx.x << 7;

    const int lr = tid & 127;
    const int lcol = (tid >> 7) << 4;
    const float* Ag = A + (size_t)(bm + lr) * K + lcol;
    const float* Bg = B + (size_t)(bn + lr) * K + lcol;

    const int wid = tid >> 5, lane = tid & 31;
    const int wm = (wid >> 2) << 6;
    const int wn = (wid & 3) << 5;
    const int g = lane >> 2;
    const int c = lane & 3;

    float acc[4][4][4];
#pragma unroll
    for (int mt = 0; mt < 4; mt++)
#pragma unroll
        for (int nt = 0; nt < 4; nt++)
#pragma unroll
            for (int e = 0; e < 4; e++) acc[mt][nt][e] = 0.f;

    const int nst = K >> 5;
    float4 pa[4], pb[4];

    // Prologue: stage 0
#pragma unroll
    for (int i = 0; i < 4; i++) {
        pa[i] = *(const float4*)(Ag + (i << 2));
        pb[i] = *(const float4*)(Bg + (i << 2));
    }
    {
        uint32_t* Asw = gsm + (size_t)lcol * GSTRIDE + lr;
        uint32_t* Bsw = Asw + GSTAGE;
#pragma unroll
        for (int i = 0; i < 4; i++) {
            Asw[(i * 4 + 0) * GSTRIDE] = f2tf32(pa[i].x);
            Asw[(i * 4 + 1) * GSTRIDE] = f2tf32(pa[i].y);
            Asw[(i * 4 + 2) * GSTRIDE] = f2tf32(pa[i].z);
            Asw[(i * 4 + 3) * GSTRIDE] = f2tf32(pa[i].w);
            Bsw[(i * 4 + 0) * GSTRIDE] = f2tf32(pb[i].x);
            Bsw[(i * 4 + 1) * GSTRIDE] = f2tf32(pb[i].y);
            Bsw[(i * 4 + 2) * GSTRIDE] = f2tf32(pb[i].z);
            Bsw[(i * 4 + 3) * GSTRIDE] = f2tf32(pb[i].w);
        }
    }
    __syncthreads();

    for (int s = 0; s < nst; s++) {
        const bool more = (s + 1 < nst);
        if (more) {
            const int k0 = (s + 1) << 5;
#pragma unroll
            for (int i = 0; i < 4; i++) {
                pa[i] = *(const float4*)(Ag + k0 + (i << 2));
                pb[i] = *(const float4*)(Bg + k0 + (i << 2));
            }
        }

        const uint32_t* As = gsm + (size_t)(s & 1) * 2 * GSTAGE;
        const uint32_t* Bs = As + GSTAGE;
#pragma unroll
        for (int ks = 0; ks < 32; ks += 8) {
            uint32_t af[4][4], bf[4][2];
#pragma unroll
            for (int mt = 0; mt < 4; mt++) {
                const int m0 = wm + (mt << 4) + g;
                af[mt][0] = As[(ks + c) * GSTRIDE + m0];
                af[mt][1] = As[(ks + c) * GSTRIDE + m0 + 8];
                af[mt][2] = As[(ks + c + 4) * GSTRIDE + m0];
                af[mt][3] = As[(ks + c + 4) * GSTRIDE + m0 + 8];
            }
#pragma unroll
            for (int nt = 0; nt < 4; nt++) {
                const int n0 = wn + (nt << 3) + g;
                bf[nt][0] = Bs[(ks + c) * GSTRIDE + n0];
                bf[nt][1] = Bs[(ks + c + 4) * GSTRIDE + n0];
            }
#pragma unroll
            for (int mt = 0; mt < 4; mt++)
#pragma unroll
                for (int nt = 0; nt < 4; nt++) {
                    asm volatile(
                        "mma.sync.aligned.m16n8k8.row.col.f32.tf32.tf32.f32 "
                        "{%0,%1,%2,%3}, {%4,%5,%6,%7}, {%8,%9}, {%0,%1,%2,%3};"
                        : "+f"(acc[mt][nt][0]), "+f"(acc[mt][nt][1]),
                          "+f"(acc[mt][nt][2]), "+f"(acc[mt][nt][3])
                        : "r"(af[mt][0]), "r"(af[mt][1]), "r"(af[mt][2]), "r"(af[mt][3]),
                          "r"(bf[nt][0]), "r"(bf[nt][1]));
                }
        }

        if (more) {
            uint32_t* Asw = gsm + (size_t)((s + 1) & 1) * 2 * GSTAGE
                          + (size_t)lcol * GSTRIDE + lr;
            uint32_t* Bsw = Asw + GSTAGE;
#pragma unroll
            for (int i = 0; i < 4; i++) {
                Asw[(i * 4 + 0) * GSTRIDE] = f2tf32(pa[i].x);
                Asw[(i * 4 + 1) * GSTRIDE] = f2tf32(pa[i].y);
                Asw[(i * 4 + 2) * GSTRIDE] = f2tf32(pa[i].z);
                Asw[(i * 4 + 3) * GSTRIDE] = f2tf32(pa[i].w);
                Bsw[(i * 4 + 0) * GSTRIDE] = f2tf32(pb[i].x);
                Bsw[(i * 4 + 1) * GSTRIDE] = f2tf32(pb[i].y);
                Bsw[(i * 4 + 2) * GSTRIDE] = f2tf32(pb[i].z);
                Bsw[(i * 4 + 3) * GSTRIDE] = f2tf32(pb[i].w);
            }
        }
        __syncthreads();
    }

    const int hcol = bn >> 7;
#pragma unroll
    for (int mt = 0; mt < 4; mt++) {
#pragma unroll
        for (int nt = 0; nt < 4; nt++) {
            const int row = bm + wm + (mt << 4) + g;
            const int col = bn + wn + (nt << 3) + (c << 1);
            float2 lo = make_float2(acc[mt][nt][0], acc[mt][nt][1]);
            float2 hi = make_float2(acc[mt][nt][2], acc[mt][nt][3]);
            if (mode == 0) {
                *(float2*)&C[(size_t)row * N + col] = lo;
                *(float2*)&C[(size_t)(row + 8) * N + col] = hi;
            } else {
                const int hd = col & (HDIM - 1);
                const int b0 = row >> 11, s0 = row & (S_LEN - 1);
                const int b1 = (row + 8) >> 11, s1 = (row + 8) & (S_LEN - 1);
                *(float2*)&C[(((size_t)(b0 * HC + hcol)) * S_LEN + s0) * HDIM + hd] = lo;
                *(float2*)&C[(((size_t)(b1 * HC + hcol)) * S_LEN + s1) * HDIM + hd] = hi;
            }
        }
    }
}

// ---------------------------------------------------------------------------
// RoPE on Q (in place)
// ---------------------------------------------------------------------------
__global__ void rope_kernel(float* __restrict__ t, const float* __restrict__ cosb,
                            const float* __restrict__ sinb, int npairs)
{
    const int i = blockIdx.x * blockDim.x + threadIdx.x;
    if (i >= npairs) return;
    const int p = i & 63;
    const int s = (i >> 6) & (S_LEN - 1);
    const int bh = i >> 17;
    const float c = cosb[(s << 6) + p];
    const float sn = sinb[(s << 6) + p];
    float2* ptr = (float2*)(t + ((size_t)bh * S_LEN + s) * HDIM + (p << 1));
    const float2 v = *ptr;
    float2 o;
    o.x = v.x * c - v.y * sn;
    o.y = v.x * sn + v.y * c;
    *ptr = o;
}

// ---------------------------------------------------------------------------
// Fused K-RoPE + split, V split -> global bf16 hi/lo (done ONCE, not per CTA)
// ---------------------------------------------------------------------------
__global__ void kv_split_kernel(const float* __restrict__ K, const float* __restrict__ V,
                                const float* __restrict__ cosb, const float* __restrict__ sinb)
{
    const int i = blockIdx.x * blockDim.x + threadIdx.x;
    const int npairs = KVTOT / 2;   // 2097152
    if (i >= npairs) return;
    const int p = i & 63;
    const int s = (i >> 6) & (S_LEN - 1);
    const int bh = i >> 17;   // 0..15
    const size_t idx = ((size_t)bh * S_LEN + s) * HDIM + (p << 1);

    const float c = cosb[(s << 6) + p];
    const float sn = sinb[(s << 6) + p];
    const float2 kv = *(const float2*)(K + idx);
    float2 kr;
    kr.x = kv.x * c - kv.y * sn;
    kr.y = kv.x * sn + kv.y * c;
    __nv_bfloat16 h0, l0, h1, l1;
    bsplit(kr.x, h0, l0); bsplit(kr.y, h1, l1);
    *(__nv_bfloat162*)&g_Kh[idx] = __nv_bfloat162(h0, h1);
    *(__nv_bfloat162*)&g_Kl[idx] = __nv_bfloat162(l0, l1);

    const float2 vv = *(const float2*)(V + idx);
    bsplit(vv.x, h0, l0); bsplit(vv.y, h1, l1);
    *(__nv_bfloat162*)&g_Vh[idx] = __nv_bfloat162(h0, h1);
    *(__nv_bfloat162*)&g_Vl[idx] = __nv_bfloat162(l0, l1);
}

// ---------------------------------------------------------------------------
// Flash attention, split-bf16 mma, double-buffered K/V from pre-split globals.
// q-tile 128 x kv-tile 64, 8 warps; warp w owns q rows [16w, 16w+16).
// ---------------------------------------------------------------------------
#define FSTR 136
#define KVST (4 * 64 * FSTR)                       // elems per KV stage
#define FLASH_SMEM ((2 * 128 * FSTR + 2 * KVST) * 2)   // 208896 B

__device__ __forceinline__ void ldsm4(uint32_t* r, const __nv_bfloat16* p) {
    uint32_t a = (uint32_t)__cvta_generic_to_shared(p);
    asm volatile("ldmatrix.sync.aligned.m8n8.x4.shared.b16 {%0,%1,%2,%3}, [%4];"
                 : "=r"(r[0]), "=r"(r[1]), "=r"(r[2]), "=r"(r[3]) : "r"(a));
}
__device__ __forceinline__ void ldsm4t(uint32_t* r, const __nv_bfloat16* p) {
    uint32_t a = (uint32_t)__cvta_generic_to_shared(p);
    asm volatile("ldmatrix.sync.aligned.m8n8.x4.trans.shared.b16 {%0,%1,%2,%3}, [%4];"
                 : "=r"(r[0]), "=r"(r[1]), "=r"(r[2]), "=r"(r[3]) : "r"(a));
}
__device__ __forceinline__ void mma_bf16(float* d, const uint32_t* a,
                                         uint32_t b0, uint32_t b1) {
    asm volatile(
        "mma.sync.aligned.m16n8k16.row.col.f32.bf16.bf16.f32 "
        "{%0,%1,%2,%3}, {%4,%5,%6,%7}, {%8,%9}, {%0,%1,%2,%3};"
        : "+f"(d[0]), "+f"(d[1]), "+f"(d[2]), "+f"(d[3])
        : "r"(a[0]), "r"(a[1]), "r"(a[2]), "r"(a[3]), "r"(b0), "r"(b1));
}

__global__ __launch_bounds__(256, 1)
void flash_bf16(const float* __restrict__ Q, float* __restrict__ O)
{
    extern __shared__ __nv_bfloat16 fsm[];
    __nv_bfloat16* Qh = fsm;
    __nv_bfloat16* Ql = Qh + 128 * FSTR;
    __nv_bfloat16* KV0 = Ql + 128 * FSTR;   // [2][Kh|Kl|Vh|Vl][64*FSTR]

    const int tid = threadIdx.x;
    const int lane = tid & 31;
    const int w = tid >> 5;
    const int g = lane >> 2;
    const int c = lane & 3;
    const int m0 = w << 4;

    const int q0 = blockIdx.x << 7;
    const int h  = blockIdx.y;
    const int b  = blockIdx.z;
    const int kvh = h >> 2;
    const float scale = 0.08838834764831845f;

    const float* Qg = Q + (((size_t)(b * H_Q + h)) * S_LEN + q0) * HDIM;
    const size_t kvbase = (size_t)(b * H_KV + kvh) * S_LEN * HDIM;
    const __nv_bfloat16* Khg = g_Kh + kvbase;
    const __nv_bfloat16* Klg = g_Kl + kvbase;
    const __nv_bfloat16* Vhg = g_Vh + kvbase;
    const __nv_bfloat16* Vlg = g_Vl + kvbase;

    // Load + split Q (scale folded in)
    for (int v = tid; v < 128 * 32; v += 256) {
        const int r = v >> 5, c4 = (v & 31) << 2;
        float4 f = *(const float4*)(Qg + (size_t)r * HDIM + c4);
        f.x *= scale; f.y *= scale; f.z *= scale; f.w *= scale;
        __nv_bfloat16 h0, l0, h1, l1, h2, l2, h3, l3;
        bsplit(f.x, h0, l0); bsplit(f.y, h1, l1);
        bsplit(f.z, h2, l2); bsplit(f.w, h3, l3);
        __nv_bfloat162* qh = (__nv_bfloat162*)&Qh[r * FSTR + c4];
        __nv_bfloat162* ql = (__nv_bfloat162*)&Ql[r * FSTR + c4];
        qh[0] = __nv_bfloat162(h0, h1); qh[1] = __nv_bfloat162(h2, h3);
        ql[0] = __nv_bfloat162(l0, l1); ql[1] = __nv_bfloat162(l2, l3);
    }

    // Preload KV stage 0 (rows: thread loads 4 x uint4 per array)
    const int pr = tid >> 2;            // 0..63 row
    const int pc = (tid & 3) << 5;      // 0,32,64,96 col base (4 x 8 cols)
    {
        __nv_bfloat16* Kh0 = KV0;
        __nv_bfloat16* Kl0 = KV0 + 64 * FSTR;
        __nv_bfloat16* Vh0 = KV0 + 2 * 64 * FSTR;
        __nv_bfloat16* Vl0 = KV0 + 3 * 64 * FSTR;
#pragma unroll
        for (int i = 0; i < 4; i++) {
            const int cc = pc + (i << 3);
            *(uint4*)&Kh0[pr * FSTR + cc] = *(const uint4*)(Khg + (size_t)pr * HDIM + cc);
            *(uint4*)&Kl0[pr * FSTR + cc] = *(const uint4*)(Klg + (size_t)pr * HDIM + cc);
            *(uint4*)&Vh0[pr * FSTR + cc] = *(const uint4*)(Vhg + (size_t)pr * HDIM + cc);
            *(uint4*)&Vl0[pr * FSTR + cc] = *(const uint4*)(Vlg + (size_t)pr * HDIM + cc);
        }
    }

    float m_run[2] = {-1e30f, -1e30f};
    float l_run[2] = {0.f, 0.f};
    float o_acc[16][4];
#pragma unroll
    for (int n = 0; n < 16; n++)
#pragma unroll
        for (int e = 0; e < 4; e++) o_acc[n][e] = 0.f;

    const int a_row = m0 + (lane & 15);
    const int a_cofs = (lane >> 4) << 3;
    const int b_rofs = (lane & 7) + ((lane >> 4) << 3);
    const int b_cofs = ((lane >> 3) & 1) << 3;
    const int v_rofs = (lane & 7) + (((lane >> 3) & 1) << 3);
    const int v_cofs = (lane >> 4) << 3;

    __syncthreads();

    const int ntiles = (q0 >> 6) + 2;
    for (int t = 0; t < ntiles; t++) {
        const int p = t & 1;
        const bool more = (t + 1 < ntiles);
        const int j1 = (t + 1) << 6;
        const __nv_bfloat16* Khp = KV0 + p * KVST;
        const __nv_bfloat16* Klp = Khp + 64 * FSTR;
        const __nv_bfloat16* Vhp = Khp + 2 * 64 * FSTR;
        const __nv_bfloat16* Vlp = Khp + 3 * 64 * FSTR;
        __nv_bfloat16* Khn = KV0 + (1 - p) * KVST;
        __nv_bfloat16* Kln = Khn + 64 * FSTR;
        __nv_bfloat16* Vhn = Khn + 2 * 64 * FSTR;
        __nv_bfloat16* Vln = Khn + 3 * 64 * FSTR;

        // --- issue LDG for next K ---
        uint4 nk[8];
        if (more) {
#pragma unroll
            for (int i = 0; i < 4; i++) {
                const int cc = pc + (i << 3);
                nk[i]     = *(const uint4*)(Khg + (size_t)(j1 + pr) * HDIM + cc);
                nk[i + 4] = *(const uint4*)(Klg + (size_t)(j1 + pr) * HDIM + cc);
            }
        }

        // ---- S = Q K^T ----
        float s[8][4];
#pragma unroll
        for (int n = 0; n < 8; n++)
#pragma unroll
            for (int e = 0; e < 4; e++) s[n][e] = 0.f;

#pragma unroll
        for (int ks = 0; ks < 8; ks++) {
            uint32_t qh[4], ql[4];
            ldsm4(qh, &Qh[a_row * FSTR + (ks << 4) + a_cofs]);
            ldsm4(ql, &Ql[a_row * FSTR + (ks << 4) + a_cofs]);
#pragma unroll
            for (int jj = 0; jj < 4; jj++) {
                uint32_t kh[4], kl[4];
                const int br = (jj << 4) + b_rofs;
                const int bc = (ks << 4) + b_cofs;
                ldsm4(kh, &Khp[br * FSTR + bc]);
                ldsm4(kl, &Klp[br * FSTR + bc]);
                mma_bf16(s[2 * jj],     qh, kh[0], kh[1]);
                mma_bf16(s[2 * jj],     qh, kl[0], kl[1]);
                mma_bf16(s[2 * jj],     ql, kh[0], kh[1]);
                mma_bf16(s[2 * jj + 1], qh, kh[2], kh[3]);
                mma_bf16(s[2 * jj + 1], qh, kl[2], kl[3]);
                mma_bf16(s[2 * jj + 1], ql, kh[2], kh[3]);
            }
        }

        // --- store next K ---
        if (more) {
#pragma unroll
            for (int i = 0; i < 4; i++) {
                const int cc = pc + (i << 3);
                *(uint4*)&Khn[pr * FSTR + cc] = nk[i];
                *(uint4*)&Kln[pr * FSTR + cc] = nk[i + 4];
            }
            // --- issue LDG for next V (reuse regs) ---
#pragma unroll
            for (int i = 0; i < 4; i++) {
                const int cc = pc + (i << 3);
                nk[i]     = *(const uint4*)(Vhg + (size_t)(j1 + pr) * HDIM + cc);
                nk[i + 4] = *(const uint4*)(Vlg + (size_t)(j1 + pr) * HDIM + cc);
            }
        }

        // ---- causal mask + online softmax ----
        const int j0 = t << 6;
        if (t >= ntiles - 2) {
            const int r0 = q0 + m0 + g, r1 = r0 + 8;
#pragma unroll
            for (int n = 0; n < 8; n++) {
                const int col = j0 + (n << 3) + (c << 1);
                if (col > r0)     s[n][0] = -1e30f;
                if (col + 1 > r0) s[n][1] = -1e30f;
                if (col > r1)     s[n][2] = -1e30f;
                if (col + 1 > r1) s[n][3] = -1e30f;
            }
        }

        float mx0 = -1e30f, mx1 = -1e30f;
#pragma unroll
        for (int n = 0; n < 8; n++) {
            mx0 = fmaxf(mx0, fmaxf(s[n][0], s[n][1]));
            mx1 = fmaxf(mx1, fmaxf(s[n][2], s[n][3]));
        }
        mx0 = fmaxf(mx0, __shfl_xor_sync(0xffffffffu, mx0, 1));
        mx0 = fmaxf(mx0, __shfl_xor_sync(0xffffffffu, mx0, 2));
        mx1 = fmaxf(mx1, __shfl_xor_sync(0xffffffffu, mx1, 1));
        mx1 = fmaxf(mx1, __shfl_xor_sync(0xffffffffu, mx1, 2));

        const float mn0 = fmaxf(m_run[0], mx0);
        const float mn1 = fmaxf(m_run[1], mx1);
        const float alpha0 = __expf(m_run[0] - mn0);
        const float alpha1 = __expf(m_run[1] - mn1);
        m_run[0] = mn0; m_run[1] = mn1;

        float sum0 = 0.f, sum1 = 0.f;
        uint32_t ph[16], pl[16];
#pragma unroll
        for (int n = 0; n < 8; n++) {
            float p0 = __expf(s[n][0] - mn0);
            float p1 = __expf(s[n][1] - mn0);
            float p2 = __expf(s[n][2] - mn1);
            float p3 = __expf(s[n][3] - mn1);
            sum0 += p0 + p1; sum1 += p2 + p3;
            __nv_bfloat16 h0, l0, h1, l1;
            bsplit(p0, h0, l0); bsplit(p1, h1, l1);
            ph[2 * n] = packbf(__bfloat162float(h0), __bfloat162float(h1));
            pl[2 * n] = packbf(__bfloat162float(l0), __bfloat162float(l1));
            bsplit(p2, h0, l0); bsplit(p3, h1, l1);
            ph[2 * n + 1] = packbf(__bfloat162float(h0), __bfloat162float(h1));
            pl[2 * n + 1] = packbf(__bfloat162float(l0), __bfloat162float(l1));
        }
        sum0 += __shfl_xor_sync(0xffffffffu, sum0, 1);
        sum0 += __shfl_xor_sync(0xffffffffu, sum0, 2);
        sum1 += __shfl_xor_sync(0xffffffffu, sum1, 1);
        sum1 += __shfl_xor_sync(0xffffffffu, sum1, 2);
        l_run[0] = l_run[0] * alpha0 + sum0;
        l_run[1] = l_run[1] * alpha1 + sum1;

#pragma unroll
        for (int n = 0; n < 16; n++) {
            o_acc[n][0] *= alpha0; o_acc[n][1] *= alpha0;
            o_acc[n][2] *= alpha1; o_acc[n][3] *= alpha1;
        }

        // ---- O += P V ----
#pragma unroll
        for (int kk = 0; kk < 4; kk++) {
            uint32_t pah[4] = {ph[4 * kk], ph[4 * kk + 1], ph[4 * kk + 2], ph[4 * kk + 3]};
            uint32_t pal[4] = {pl[4 * kk], pl[4 * kk + 1], pl[4 * kk + 2], pl[4 * kk + 3]};
#pragma unroll
            for (int jj = 0; jj < 8; jj++) {
                uint32_t vh[4], vl[4];
                const int vr = (kk << 4) + v_rofs;
                const int vc = (jj << 4) + v_cofs;
                ldsm4t(vh, &Vhp[vr * FSTR + vc]);
                ldsm4t(vl, &Vlp[vr * FSTR + vc]);
                mma_bf16(o_acc[2 * jj],     pah, vh[0], vh[1]);
                mma_bf16(o_acc[2 * jj],     pal, vh[0], vh[1]);
                mma_bf16(o_acc[2 * jj],     pah, vl[0], vl[1]);
                mma_bf16(o_acc[2 * jj + 1], pah, vh[2], vh[3]);
                mma_bf16(o_acc[2 * jj + 1], pal, vh[2], vh[3]);
                mma_bf16(o_acc[2 * jj + 1], pah, vl[2], vl[3]);
            }
        }

        // --- store next V ---
        if (more) {
#pragma unroll
            for (int i = 0; i < 4; i++) {
                const int cc = pc + (i << 3);
                *(uint4*)&Vhn[pr * FSTR + cc] = nk[i];
                *(uint4*)&Vln[pr * FSTR + cc] = nk[i + 4];
            }
        }
        __syncthreads();
    }

    const float inv0 = 1.f / l_run[0];
    const float inv1 = 1.f / l_run[1];
    const int s0 = q0 + m0 + g;
    const int s1 = s0 + 8;
    float* d0 = O + (((size_t)(b * S_LEN + s0)) * H_Q + h) * HDIM;
    float* d1 = O + (((size_t)(b * S_LEN + s1)) * H_Q + h) * HDIM;
#pragma unroll
    for (int n = 0; n < 16; n++) {
        const int col = (n << 3) + (c << 1);
        *(float2*)(d0 + col) = make_float2(o_acc[n][0] * inv0, o_acc[n][1] * inv0);
        *(float2*)(d1 + col) = make_float2(o_acc[n][2] * inv1, o_acc[n][3] * inv1);
    }
}

// ---------------------------------------------------------------------------
extern "C" void kernel_launch(void* const* d_in, const int* in_sizes, int n_in,
                              void* d_out, int out_size)
{
    const float* x    = (const float*)d_in[0];
    const float* wq   = (const float*)d_in[1];
    const float* wk   = (const float*)d_in[2];
    const float* wv   = (const float*)d_in[3];
    const float* wo   = (const float*)d_in[4];
    const float* cosb = (const float*)d_in[5];
    const float* sinb = (const float*)d_in[6];
    float* out = (float*)d_out;

    float *Q, *A;
    cudaGetSymbolAddress((void**)&Q, g_Q);
    cudaGetSymbolAddress((void**)&A, g_A);
    // K/V projections write into g_A's space? No — reuse g_A only after flash.
    // K and V fp32 staging: use the tail of g_Q? Sizes: g_Q is exactly Q.
    // Use dedicated fp32 staging inside g_A (A is written by flash later):
    //   g_A holds 16.8M floats; K fp32 needs 4.2M, V fp32 needs 4.2M -> fits.
    float* Kf = A;                     // staging: [B, KV, S, HD]
    float* Vf = A + KVTOT;             // staging
    // (kv_split consumes these before flash writes g_A.)

    const int M = BATCH * S_LEN;   // 4096

    cudaFuncSetAttribute(tf32gemm_db, cudaFuncAttributeMaxDynamicSharedMemorySize, GEMM_SMEM);
    cudaFuncSetAttribute(flash_bf16, cudaFuncAttributeMaxDynamicSharedMemorySize, FLASH_SMEM);

    // QKV projections (tf32, double-buffered)
    tf32gemm_db<<<dim3((H_Q * HDIM) / 128, M / 128), 256, GEMM_SMEM>>>(x, wq, Q, M, H_Q * HDIM, D_DIM, 1, H_Q);
    tf32gemm_db<<<dim3((H_KV * HDIM) / 128, M / 128), 256, GEMM_SMEM>>>(x, wk, Kf, M, H_KV * HDIM, D_DIM, 1, H_KV);
    tf32gemm_db<<<dim3((H_KV * HDIM) / 128, M / 128), 256, GEMM_SMEM>>>(x, wv, Vf, M, H_KV * HDIM, D_DIM, 1, H_KV);

    // RoPE on Q; fused K-RoPE + split and V split to global bf16
    const int qpairs = BATCH * H_Q * S_LEN * (HDIM / 2);
    rope_kernel<<<(qpairs + 255) / 256, 256>>>(Q, cosb, sinb, qpairs);
    kv_split_kernel<<<(KVTOT / 2 + 255) / 256, 256>>>(Kf, Vf, cosb, sinb);

    // Flash attention (double-buffered, pre-split K/V)
    flash_bf16<<<dim3(S_LEN / 128, H_Q, BATCH), 256, FLASH_SMEM>>>(Q, A);

    // Output projection
    tf32gemm_db<<<dim3(D_DIM / 128, M / 128), 256, GEMM_SMEM>>>(A, wo, out, M, D_DIM, D_DIM, 0, 0);
}

// round 7
// speedup vs baseline: 1.2359x; 1.2359x over previous
#include <cuda_runtime.h>
#include <cuda_bf16.h>
#include <cuda_fp16.h>
#include <cstdint>

#define S_LEN 2048
#define D_DIM 4096
#define H_Q   32
#define H_KV  8
#define HDIM  128
#define BATCH 2

// Scratch (allocation-free rule: __device__ globals)
__device__ float g_Q[BATCH * H_Q * S_LEN * HDIM];   // [B, H, S, HD]
__device__ float g_K[BATCH * H_KV * S_LEN * HDIM];  // [B, KV, S, HD]
__device__ float g_V[BATCH * H_KV * S_LEN * HDIM];  // [B, KV, S, HD]
__device__ float g_A[BATCH * S_LEN * H_Q * HDIM];   // [B, S, H, HD]

__device__ __forceinline__ uint32_t packh(float a, float b) {
    __half2 h = __floats2half2_rn(a, b);
    return *(uint32_t*)&h;
}

// ---------------------------------------------------------------------------
// FP16 tensor-core NT GEMM: C[m,n] = sum_k A[m,k] * B[n,k]  (fp32 accumulate)
// CTA tile 128x128, BK=32, 256 threads = 8 warps (2m x 4n), warp tile 64x32.
// Each warp: 4x4 grid of mma.m16n8k16 tiles (half the instrs of tf32 k8).
// Smem: K-pair-transposed, packed fp16x2 words, stride 136 (conflict-free).
// mode 0: C row-major [M,N].  mode 1: head-permuted store to [B, HC, S, HD].
// ---------------------------------------------------------------------------
#define GSTRIDE 136

__global__ __launch_bounds__(256)
void h16gemm_nt(const float* __restrict__ A, const float* __restrict__ B,
                float* __restrict__ C, int M, int N, int K, int mode, int HC)
{
    __shared__ uint32_t As[16 * GSTRIDE];   // [kpair][m] packed (2k,2k+1)
    __shared__ uint32_t Bs[16 * GSTRIDE];

    const int tid = threadIdx.x;
    const int bm = blockIdx.y << 7;
    const int bn = blockIdx.x << 7;

    // Global load mapping: thread -> row (tid&127), 16 cols from (tid>>7)*16.
    const int lr = tid & 127;
    const int lcol = (tid >> 7) << 4;       // 0 or 16 (k-elements)
    const int lkp = lcol >> 1;              // kpair base: 0 or 8
    const float* Ag = A + (size_t)(bm + lr) * K + lcol;
    const float* Bg = B + (size_t)(bn + lr) * K + lcol;

    uint32_t* Asw = &As[(size_t)lkp * GSTRIDE + lr];
    uint32_t* Bsw = &Bs[(size_t)lkp * GSTRIDE + lr];

    float4 pa[4], pb[4];
#pragma unroll
    for (int i = 0; i < 4; i++) {
        pa[i] = *(const float4*)(Ag + (i << 2));
        pb[i] = *(const float4*)(Bg + (i << 2));
    }

    const int wid = tid >> 5, lane = tid & 31;
    const int wm = (wid >> 2) << 6;   // 0 or 64
    const int wn = (wid & 3) << 5;    // 0,32,64,96
    const int g = lane >> 2;          // 0..7
    const int c = lane & 3;           // 0..3

    float acc[4][4][4];
#pragma unroll
    for (int mt = 0; mt < 4; mt++)
#pragma unroll
        for (int nt = 0; nt < 4; nt++)
#pragma unroll
            for (int e = 0; e < 4; e++) acc[mt][nt][e] = 0.f;

    int k0 = 0;
    for (;;) {
        // Store stage: each float4 -> 2 packed kpair words, conflict-free.
#pragma unroll
        for (int i = 0; i < 4; i++) {
            Asw[(i * 2 + 0) * GSTRIDE] = packh(pa[i].x, pa[i].y);
            Asw[(i * 2 + 1) * GSTRIDE] = packh(pa[i].z, pa[i].w);
            Bsw[(i * 2 + 0) * GSTRIDE] = packh(pb[i].x, pb[i].y);
            Bsw[(i * 2 + 1) * GSTRIDE] = packh(pb[i].z, pb[i].w);
        }
        __syncthreads();

        k0 += 32;
        const bool more = (k0 < K);
        if (more) {
#pragma unroll
            for (int i = 0; i < 4; i++) {
                pa[i] = *(const float4*)(Ag + k0 + (i << 2));
                pb[i] = *(const float4*)(Bg + k0 + (i << 2));
            }
        }

        // 2 k16-steps per stage (kpair bases 0 and 8)
#pragma unroll
        for (int kq = 0; kq < 16; kq += 8) {
            uint32_t af[4][4], bf[4][2];
#pragma unroll
            for (int mt = 0; mt < 4; mt++) {
                const int m0 = wm + (mt << 4) + g;
                af[mt][0] = As[(kq + c) * GSTRIDE + m0];
                af[mt][1] = As[(kq + c) * GSTRIDE + m0 + 8];
                af[mt][2] = As[(kq + c + 4) * GSTRIDE + m0];
                af[mt][3] = As[(kq + c + 4) * GSTRIDE + m0 + 8];
            }
#pragma unroll
            for (int nt = 0; nt < 4; nt++) {
                const int n0 = wn + (nt << 3) + g;
                bf[nt][0] = Bs[(kq + c) * GSTRIDE + n0];
                bf[nt][1] = Bs[(kq + c + 4) * GSTRIDE + n0];
            }
#pragma unroll
            for (int mt = 0; mt < 4; mt++)
#pragma unroll
                for (int nt = 0; nt < 4; nt++) {
                    asm volatile(
                        "mma.sync.aligned.m16n8k16.row.col.f32.f16.f16.f32 "
                        "{%0,%1,%2,%3}, {%4,%5,%6,%7}, {%8,%9}, {%0,%1,%2,%3};"
                        : "+f"(acc[mt][nt][0]), "+f"(acc[mt][nt][1]),
                          "+f"(acc[mt][nt][2]), "+f"(acc[mt][nt][3])
                        : "r"(af[mt][0]), "r"(af[mt][1]), "r"(af[mt][2]), "r"(af[mt][3]),
                          "r"(bf[nt][0]), "r"(bf[nt][1]));
                }
        }
        if (!more) break;
        __syncthreads();
    }

    // Epilogue: c0,c1 -> (row, 2c, 2c+1); c2,c3 -> (row+8, same cols).
    const int hcol = bn >> 7;
#pragma unroll
    for (int mt = 0; mt < 4; mt++) {
#pragma unroll
        for (int nt = 0; nt < 4; nt++) {
            const int row = bm + wm + (mt << 4) + g;
            const int col = bn + wn + (nt << 3) + (c << 1);
            float2 lo = make_float2(acc[mt][nt][0], acc[mt][nt][1]);
            float2 hi = make_float2(acc[mt][nt][2], acc[mt][nt][3]);
            if (mode == 0) {
                *(float2*)&C[(size_t)row * N + col] = lo;
                *(float2*)&C[(size_t)(row + 8) * N + col] = hi;
            } else {
                const int hd = col & (HDIM - 1);
                const int b0 = row >> 11, s0 = row & (S_LEN - 1);
                const int b1 = (row + 8) >> 11, s1 = (row + 8) & (S_LEN - 1);
                *(float2*)&C[(((size_t)(b0 * HC + hcol)) * S_LEN + s0) * HDIM + hd] = lo;
                *(float2*)&C[(((size_t)(b1 * HC + hcol)) * S_LEN + s1) * HDIM + hd] = hi;
            }
        }
    }
}

// ---------------------------------------------------------------------------
// RoPE (unchanged)
// ---------------------------------------------------------------------------
__global__ void rope_kernel(float* __restrict__ t, const float* __restrict__ cosb,
                            const float* __restrict__ sinb, int npairs)
{
    const int i = blockIdx.x * blockDim.x + threadIdx.x;
    if (i >= npairs) return;
    const int p = i & 63;
    const int s = (i >> 6) & (S_LEN - 1);
    const int bh = i >> 17;
    const float c = cosb[(s << 6) + p];
    const float sn = sinb[(s << 6) + p];
    float2* ptr = (float2*)(t + ((size_t)bh * S_LEN + s) * HDIM + (p << 1));
    const float2 v = *ptr;
    float2 o;
    o.x = v.x * c - v.y * sn;
    o.y = v.x * sn + v.y * c;
    *ptr = o;
}

// ---------------------------------------------------------------------------
// Flash attention: split-bf16 mma (proven R4 version, unchanged)
// ---------------------------------------------------------------------------
#define FSTR 136
#define FLASH_SMEM ((2 * 128 * FSTR + 4 * 64 * FSTR) * 2)

__device__ __forceinline__ void ldsm4(uint32_t* r, const __nv_bfloat16* p) {
    uint32_t a = (uint32_t)__cvta_generic_to_shared(p);
    asm volatile("ldmatrix.sync.aligned.m8n8.x4.shared.b16 {%0,%1,%2,%3}, [%4];"
                 : "=r"(r[0]), "=r"(r[1]), "=r"(r[2]), "=r"(r[3]) : "r"(a));
}
__device__ __forceinline__ void ldsm4t(uint32_t* r, const __nv_bfloat16* p) {
    uint32_t a = (uint32_t)__cvta_generic_to_shared(p);
    asm volatile("ldmatrix.sync.aligned.m8n8.x4.trans.shared.b16 {%0,%1,%2,%3}, [%4];"
                 : "=r"(r[0]), "=r"(r[1]), "=r"(r[2]), "=r"(r[3]) : "r"(a));
}
__device__ __forceinline__ void mma_bf16(float* d, const uint32_t* a,
                                         uint32_t b0, uint32_t b1) {
    asm volatile(
        "mma.sync.aligned.m16n8k16.row.col.f32.bf16.bf16.f32 "
        "{%0,%1,%2,%3}, {%4,%5,%6,%7}, {%8,%9}, {%0,%1,%2,%3};"
        : "+f"(d[0]), "+f"(d[1]), "+f"(d[2]), "+f"(d[3])
        : "r"(a[0]), "r"(a[1]), "r"(a[2]), "r"(a[3]), "r"(b0), "r"(b1));
}
__device__ __forceinline__ void bsplit(float x, __nv_bfloat16& h, __nv_bfloat16& l) {
    h = __float2bfloat16(x);
    l = __float2bfloat16(x - __bfloat162float(h));
}
__device__ __forceinline__ uint32_t packbf(float a, float b) {
    __nv_bfloat162 t = __floats2bfloat162_rn(a, b);
    return *(uint32_t*)&t;
}

__global__ __launch_bounds__(256, 1)
void flash_bf16(const float* __restrict__ Q, const float* __restrict__ K,
                const float* __restrict__ V, float* __restrict__ O)
{
    extern __shared__ __nv_bfloat16 fsm[];
    __nv_bfloat16* Qh = fsm;
    __nv_bfloat16* Ql = Qh + 128 * FSTR;
    __nv_bfloat16* Kh = Ql + 128 * FSTR;
    __nv_bfloat16* Kl = Kh + 64 * FSTR;
    __nv_bfloat16* Vh = Kl + 64 * FSTR;
    __nv_bfloat16* Vl = Vh + 64 * FSTR;

    const int tid = threadIdx.x;
    const int lane = tid & 31;
    const int w = tid >> 5;
    const int g = lane >> 2;
    const int c = lane & 3;
    const int m0 = w << 4;

    const int q0 = blockIdx.x << 7;
    const int h  = blockIdx.y;
    const int b  = blockIdx.z;
    const int kvh = h >> 2;
    const float scale = 0.08838834764831845f;

    const float* Qg = Q + (((size_t)(b * H_Q + h)) * S_LEN + q0) * HDIM;
    const float* Kg = K + ((size_t)(b * H_KV + kvh)) * S_LEN * HDIM;
    const float* Vg = V + ((size_t)(b * H_KV + kvh)) * S_LEN * HDIM;

    for (int v = tid; v < 128 * 32; v += 256) {
        const int r = v >> 5, c4 = (v & 31) << 2;
        float4 f = *(const float4*)(Qg + (size_t)r * HDIM + c4);
        f.x *= scale; f.y *= scale; f.z *= scale; f.w *= scale;
        __nv_bfloat16 h0, l0, h1, l1, h2, l2, h3, l3;
        bsplit(f.x, h0, l0); bsplit(f.y, h1, l1);
        bsplit(f.z, h2, l2); bsplit(f.w, h3, l3);
        __nv_bfloat162* qh = (__nv_bfloat162*)&Qh[r * FSTR + c4];
        __nv_bfloat162* ql = (__nv_bfloat162*)&Ql[r * FSTR + c4];
        qh[0] = __nv_bfloat162(h0, h1); qh[1] = __nv_bfloat162(h2, h3);
        ql[0] = __nv_bfloat162(l0, l1); ql[1] = __nv_bfloat162(l2, l3);
    }

    float m_run[2] = {-1e30f, -1e30f};
    float l_run[2] = {0.f, 0.f};
    float o_acc[16][4];
#pragma unroll
    for (int n = 0; n < 16; n++)
#pragma unroll
        for (int e = 0; e < 4; e++) o_acc[n][e] = 0.f;

    const int a_row = m0 + (lane & 15);
    const int a_cofs = (lane >> 4) << 3;
    const int b_rofs = (lane & 7) + ((lane >> 4) << 3);
    const int b_cofs = ((lane >> 3) & 1) << 3;
    const int v_rofs = (lane & 7) + (((lane >> 3) & 1) << 3);
    const int v_cofs = (lane >> 4) << 3;

    const int ntiles = (q0 >> 6) + 2;
    for (int t = 0; t < ntiles; t++) {
        const int j0 = t << 6;
        __syncthreads();

        for (int v = tid; v < 64 * 32; v += 256) {
            const int r = v >> 5, c4 = (v & 31) << 2;
            float4 fk = *(const float4*)(Kg + (size_t)(j0 + r) * HDIM + c4);
            float4 fv = *(const float4*)(Vg + (size_t)(j0 + r) * HDIM + c4);
            __nv_bfloat16 h0, l0, h1, l1, h2, l2, h3, l3;
            bsplit(fk.x, h0, l0); bsplit(fk.y, h1, l1);
            bsplit(fk.z, h2, l2); bsplit(fk.w, h3, l3);
            __nv_bfloat162* kh = (__nv_bfloat162*)&Kh[r * FSTR + c4];
            __nv_bfloat162* kl = (__nv_bfloat162*)&Kl[r * FSTR + c4];
            kh[0] = __nv_bfloat162(h0, h1); kh[1] = __nv_bfloat162(h2, h3);
            kl[0] = __nv_bfloat162(l0, l1); kl[1] = __nv_bfloat162(l2, l3);
            bsplit(fv.x, h0, l0); bsplit(fv.y, h1, l1);
            bsplit(fv.z, h2, l2); bsplit(fv.w, h3, l3);
            __nv_bfloat162* vh = (__nv_bfloat162*)&Vh[r * FSTR + c4];
            __nv_bfloat162* vl = (__nv_bfloat162*)&Vl[r * FSTR + c4];
            vh[0] = __nv_bfloat162(h0, h1); vh[1] = __nv_bfloat162(h2, h3);
            vl[0] = __nv_bfloat162(l0, l1); vl[1] = __nv_bfloat162(l2, l3);
        }
        __syncthreads();

        float s[8][4];
#pragma unroll
        for (int n = 0; n < 8; n++)
#pragma unroll
            for (int e = 0; e < 4; e++) s[n][e] = 0.f;

#pragma unroll
        for (int ks = 0; ks < 8; ks++) {
            uint32_t qh[4], ql[4];
            ldsm4(qh, &Qh[a_row * FSTR + (ks << 4) + a_cofs]);
            ldsm4(ql, &Ql[a_row * FSTR + (ks << 4) + a_cofs]);
#pragma unroll
            for (int jj = 0; jj < 4; jj++) {
                uint32_t kh[4], kl[4];
                const int br = (jj << 4) + b_rofs;
                const int bc = (ks << 4) + b_cofs;
                ldsm4(kh, &Kh[br * FSTR + bc]);
                ldsm4(kl, &Kl[br * FSTR + bc]);
                mma_bf16(s[2 * jj],     qh, kh[0], kh[1]);
                mma_bf16(s[2 * jj],     qh, kl[0], kl[1]);
                mma_bf16(s[2 * jj],     ql, kh[0], kh[1]);
                mma_bf16(s[2 * jj + 1], qh, kh[2], kh[3]);
                mma_bf16(s[2 * jj + 1], qh, kl[2], kl[3]);
                mma_bf16(s[2 * jj + 1], ql, kh[2], kh[3]);
            }
        }

        if (t >= ntiles - 2) {
            const int r0 = q0 + m0 + g, r1 = r0 + 8;
#pragma unroll
            for (int n = 0; n < 8; n++) {
                const int col = j0 + (n << 3) + (c << 1);
                if (col > r0)     s[n][0] = -1e30f;
                if (col + 1 > r0) s[n][1] = -1e30f;
                if (col > r1)     s[n][2] = -1e30f;
                if (col + 1 > r1) s[n][3] = -1e30f;
            }
        }

        float mx0 = -1e30f, mx1 = -1e30f;
#pragma unroll
        for (int n = 0; n < 8; n++) {
            mx0 = fmaxf(mx0, fmaxf(s[n][0], s[n][1]));
            mx1 = fmaxf(mx1, fmaxf(s[n][2], s[n][3]));
        }
        mx0 = fmaxf(mx0, __shfl_xor_sync(0xffffffffu, mx0, 1));
        mx0 = fmaxf(mx0, __shfl_xor_sync(0xffffffffu, mx0, 2));
        mx1 = fmaxf(mx1, __shfl_xor_sync(0xffffffffu, mx1, 1));
        mx1 = fmaxf(mx1, __shfl_xor_sync(0xffffffffu, mx1, 2));

        const float mn0 = fmaxf(m_run[0], mx0);
        const float mn1 = fmaxf(m_run[1], mx1);
        const float alpha0 = __expf(m_run[0] - mn0);
        const float alpha1 = __expf(m_run[1] - mn1);
        m_run[0] = mn0; m_run[1] = mn1;

        float sum0 = 0.f, sum1 = 0.f;
        uint32_t ph[16], pl[16];
#pragma unroll
        for (int n = 0; n < 8; n++) {
            float p0 = __expf(s[n][0] - mn0);
            float p1 = __expf(s[n][1] - mn0);
            float p2 = __expf(s[n][2] - mn1);
            float p3 = __expf(s[n][3] - mn1);
            sum0 += p0 + p1; sum1 += p2 + p3;
            __nv_bfloat16 h0, l0, h1, l1;
            bsplit(p0, h0, l0); bsplit(p1, h1, l1);
            ph[2 * n] = packbf(__bfloat162float(h0), __bfloat162float(h1));
            pl[2 * n] = packbf(__bfloat162float(l0), __bfloat162float(l1));
            bsplit(p2, h0, l0); bsplit(p3, h1, l1);
            ph[2 * n + 1] = packbf(__bfloat162float(h0), __bfloat162float(h1));
            pl[2 * n + 1] = packbf(__bfloat162float(l0), __bfloat162float(l1));
        }
        sum0 += __shfl_xor_sync(0xffffffffu, sum0, 1);
        sum0 += __shfl_xor_sync(0xffffffffu, sum0, 2);
        sum1 += __shfl_xor_sync(0xffffffffu, sum1, 1);
        sum1 += __shfl_xor_sync(0xffffffffu, sum1, 2);
        l_run[0] = l_run[0] * alpha0 + sum0;
        l_run[1] = l_run[1] * alpha1 + sum1;

#pragma unroll
        for (int n = 0; n < 16; n++) {
            o_acc[n][0] *= alpha0; o_acc[n][1] *= alpha0;
            o_acc[n][2] *= alpha1; o_acc[n][3] *= alpha1;
        }

#pragma unroll
        for (int kk = 0; kk < 4; kk++) {
            uint32_t pah[4] = {ph[4 * kk], ph[4 * kk + 1], ph[4 * kk + 2], ph[4 * kk + 3]};
            uint32_t pal[4] = {pl[4 * kk], pl[4 * kk + 1], pl[4 * kk + 2], pl[4 * kk + 3]};
#pragma unroll
            for (int jj = 0; jj < 8; jj++) {
                uint32_t vh[4], vl[4];
                const int vr = (kk << 4) + v_rofs;
                const int vc = (jj << 4) + v_cofs;
                ldsm4t(vh, &Vh[vr * FSTR + vc]);
                ldsm4t(vl, &Vl[vr * FSTR + vc]);
                mma_bf16(o_acc[2 * jj],     pah, vh[0], vh[1]);
                mma_bf16(o_acc[2 * jj],     pal, vh[0], vh[1]);
                mma_bf16(o_acc[2 * jj],     pah, vl[0], vl[1]);
                mma_bf16(o_acc[2 * jj + 1], pah, vh[2], vh[3]);
                mma_bf16(o_acc[2 * jj + 1], pal, vh[2], vh[3]);
                mma_bf16(o_acc[2 * jj + 1], pah, vl[2], vl[3]);
            }
        }
    }

    const float inv0 = 1.f / l_run[0];
    const float inv1 = 1.f / l_run[1];
    const int s0 = q0 + m0 + g;
    const int s1 = s0 + 8;
    float* d0 = O + (((size_t)(b * S_LEN + s0)) * H_Q + h) * HDIM;
    float* d1 = O + (((size_t)(b * S_LEN + s1)) * H_Q + h) * HDIM;
#pragma unroll
    for (int n = 0; n < 16; n++) {
        const int col = (n << 3) + (c << 1);
        *(float2*)(d0 + col) = make_float2(o_acc[n][0] * inv0, o_acc[n][1] * inv0);
        *(float2*)(d1 + col) = make_float2(o_acc[n][2] * inv1, o_acc[n][3] * inv1);
    }
}

// ---------------------------------------------------------------------------
extern "C" void kernel_launch(void* const* d_in, const int* in_sizes, int n_in,
                              void* d_out, int out_size)
{
    const float* x    = (const float*)d_in[0];
    const float* wq   = (const float*)d_in[1];
    const float* wk   = (const float*)d_in[2];
    const float* wv   = (const float*)d_in[3];
    const float* wo   = (const float*)d_in[4];
    const float* cosb = (const float*)d_in[5];
    const float* sinb = (const float*)d_in[6];
    float* out = (float*)d_out;

    float *Q, *K, *V, *A;
    cudaGetSymbolAddress((void**)&Q, g_Q);
    cudaGetSymbolAddress((void**)&K, g_K);
    cudaGetSymbolAddress((void**)&V, g_V);
    cudaGetSymbolAddress((void**)&A, g_A);

    const int M = BATCH * S_LEN;   // 4096

    // QKV projections (fp16 mma, head-permuted stores)
    h16gemm_nt<<<dim3((H_Q * HDIM) / 128, M / 128), 256>>>(x, wq, Q, M, H_Q * HDIM, D_DIM, 1, H_Q);
    h16gemm_nt<<<dim3((H_KV * HDIM) / 128, M / 128), 256>>>(x, wk, K, M, H_KV * HDIM, D_DIM, 1, H_KV);
    h16gemm_nt<<<dim3((H_KV * HDIM) / 128, M / 128), 256>>>(x, wv, V, M, H_KV * HDIM, D_DIM, 1, H_KV);

    // RoPE on Q and K
    const int qpairs = BATCH * H_Q * S_LEN * (HDIM / 2);
    const int kpairs = BATCH * H_KV * S_LEN * (HDIM / 2);
    rope_kernel<<<(qpairs + 255) / 256, 256>>>(Q, cosb, sinb, qpairs);
    rope_kernel<<<(kpairs + 255) / 256, 256>>>(K, cosb, sinb, kpairs);

    // Flash attention (split-bf16 mma, proven)
    cudaFuncSetAttribute(flash_bf16, cudaFuncAttributeMaxDynamicSharedMemorySize, FLASH_SMEM);
    flash_bf16<<<dim3(S_LEN / 128, H_Q, BATCH), 256, FLASH_SMEM>>>(Q, K, V, A);

    // Output projection (fp16 mma)
    h16gemm_nt<<<dim3(D_DIM / 128, M / 128), 256>>>(A, wo, out, M, D_DIM, D_DIM, 0, 0);
}